// round 5
// baseline (speedup 1.0000x reference)
#include <cuda_runtime.h>

typedef unsigned long long u64;

#define BATCH 32
#define SEQ   500
#define DM    128
#define HID   64
#define G3    192        // 3*HID
#define NROW  16000      // BATCH*SEQ
#define NLIB  2145
#define FFD   128

// ---------------- scratch (device globals; no allocation allowed) ----------
__device__ float g_xp0[BATCH * SEQ * G3];    // 12.3 MB: input projections for GRU L0
__device__ float g_bufA[NROW * HID];         // GRU output
__device__ float g_bufB[NROW * HID];         // SINDy layer 0 output

// ---------------- packed f32x2 helpers ------------------------------------
__device__ __forceinline__ u64 fma2(u64 a, u64 b, u64 c) {
    u64 d; asm("fma.rn.f32x2 %0, %1, %2, %3;" : "=l"(d) : "l"(a), "l"(b), "l"(c)); return d;
}
__device__ __forceinline__ u64 pack2(float x, float y) {
    u64 r; asm("mov.b64 %0, {%1, %2};" : "=l"(r) : "f"(x), "f"(y)); return r;
}
__device__ __forceinline__ u64 bcast2(float x) {
    u64 r; asm("mov.b64 %0, {%1, %1};" : "=l"(r) : "f"(x)); return r;
}
__device__ __forceinline__ void unpack2(u64 v, float& x, float& y) {
    asm("mov.b64 {%0, %1}, %2;" : "=f"(x), "=f"(y) : "l"(v));
}
__device__ __forceinline__ float hadd2(u64 v) { float x, y; unpack2(v, x, y); return x + y; }

__device__ __forceinline__ float sigf(float v) { return 1.0f / (1.0f + __expf(-v)); }

// ============================================================================
// K1: g_xp0[row][g] = bih0[g] + sum_k x[row][k] * Wih0[g][k]
// 500 blocks x 192 threads; 32 rows per block; packed-k FMA.
// ============================================================================
__global__ __launch_bounds__(192) void k_xp0(const float* __restrict__ x,
                                             const float* __restrict__ Wih0,
                                             const float* __restrict__ bih0) {
    __shared__ u64 xs[32 * 64];   // 32 rows x 64 packed-k
    const int g = threadIdx.x;
    const u64* x2 = (const u64*)x + (size_t)blockIdx.x * 2048;
    for (int idx = g; idx < 2048; idx += 192) xs[idx] = x2[idx];
    __syncthreads();

    const u64* wp = (const u64*)Wih0 + (size_t)g * 64;
    u64 acc[32];
#pragma unroll
    for (int r = 0; r < 32; r++) acc[r] = 0ull;

    for (int kk = 0; kk < 64; kk++) {
        u64 w = __ldg(&wp[kk]);
#pragma unroll
        for (int r = 0; r < 32; r++) acc[r] = fma2(w, xs[r * 64 + kk], acc[r]);
    }
    const float bias = bih0[g];
    const int row0 = blockIdx.x * 32;
#pragma unroll
    for (int r = 0; r < 32; r++)
        g_xp0[(size_t)(row0 + r) * G3 + g] = hadd2(acc[r]) + bias;
}

// ============================================================================
// K2: fused 2-layer GRU. One block per batch element; 192 threads (one per
// gate row). Whh0 in shared (padded), Wih1/Whh1 rows register-resident.
// Writes layer-1 hidden stream to g_bufA.
// ============================================================================
#define GRU_SMEM (192 * 33 * 8 + (64 + 64 + 192 * 5) * 4)

__global__ __launch_bounds__(192, 1) void k_gru(const float* __restrict__ Whh0,
                                                const float* __restrict__ Wih1,
                                                const float* __restrict__ Whh1,
                                                const float* __restrict__ bhh0,
                                                const float* __restrict__ bih1,
                                                const float* __restrict__ bhh1) {
    extern __shared__ char sm[];
    u64*   w0s = (u64*)sm;                       // [192][33] padded
    float* h0s = (float*)(sm + 192 * 33 * 8);    // 64
    float* h1s = h0s + 64;                       // 64
    float* xps = h1s + 64;                       // 192
    float* ghs = xps + 192;                      // 192
    float* bh0 = ghs + 192;                      // 192
    float* bi1 = bh0 + 192;                      // 192
    float* bh1 = bi1 + 192;                      // 192

    const int g = threadIdx.x;
    const int b = blockIdx.x;

    // stage Whh0 (coalesced global u64)
    const u64* W0g = (const u64*)Whh0;
    for (int idx = g; idx < 192 * 32; idx += 192) {
        int gg = idx >> 5, kk = idx & 31;
        w0s[gg * 33 + kk] = W0g[idx];
    }
    // register-resident rows of Wih1 / Whh1
    u64 wi1r[32], w1r[32];
    const u64* Wi1g = (const u64*)Wih1 + (size_t)g * 32;
    const u64* W1g  = (const u64*)Whh1 + (size_t)g * 32;
#pragma unroll
    for (int kk = 0; kk < 32; kk++) { wi1r[kk] = __ldg(&Wi1g[kk]); w1r[kk] = __ldg(&W1g[kk]); }

    bh0[g] = bhh0[g]; bi1[g] = bih1[g]; bh1[g] = bhh1[g];
    if (g < 64) { h0s[g] = 0.0f; h1s[g] = 0.0f; }
    __syncthreads();

    const float* xprow = g_xp0 + (size_t)b * SEQ * G3;
    float* outp = g_bufA + (size_t)b * SEQ * HID;
    const u64* h02 = (const u64*)h0s;
    const u64* h12 = (const u64*)h1s;
    const u64* myw0 = w0s + g * 33;

    float xcur = xprow[g];   // prefetch t=0
    for (int t = 0; t < SEQ; t++) {
        xps[g] = xcur;
        float xnext = (t < SEQ - 1) ? xprow[(size_t)(t + 1) * G3 + g] : 0.0f; // early LDG

        // matvec1: Whh0 @ h0
        u64 acc = 0ull;
#pragma unroll
        for (int kk = 0; kk < 32; kk++) acc = fma2(myw0[kk], h02[kk], acc);
        ghs[g] = hadd2(acc) + bh0[g];
        __syncthreads();                                   // (A)

        if (g < 64) {
            float r = sigf(xps[g] + ghs[g]);
            float z = sigf(xps[64 + g] + ghs[64 + g]);
            float n = tanhf(xps[128 + g] + r * ghs[128 + g]);
            h0s[g] = (1.0f - z) * n + z * h0s[g];
        }
        __syncthreads();                                   // (B)

        // matvec2: Wih1 @ h0_new  and  Whh1 @ h1
        u64 a1 = 0ull, a2 = 0ull;
#pragma unroll
        for (int kk = 0; kk < 32; kk++) {
            u64 hv0 = h02[kk], hv1 = h12[kk];
            a1 = fma2(wi1r[kk], hv0, a1);
            a2 = fma2(w1r[kk], hv1, a2);
        }
        xps[g] = hadd2(a1) + bi1[g];
        ghs[g] = hadd2(a2) + bh1[g];
        __syncthreads();                                   // (C)

        if (g < 64) {
            float r = sigf(xps[g] + ghs[g]);
            float z = sigf(xps[64 + g] + ghs[64 + g]);
            float n = tanhf(xps[128 + g] + r * ghs[128 + g]);
            float h = (1.0f - z) * n + z * h1s[g];
            h1s[g] = h;
            outp[(size_t)t * HID + g] = h;
        }
        __syncthreads();                                   // (D)
        xcur = xnext;
    }
}

// ============================================================================
// K3: fused SINDy layer (Theta@coef + LN1 + FF(gelu) + LN2) for a 128-row tile.
// 125 blocks x 256 threads. Theta generated on the fly from z (with appended
// 1.0 column) via a per-block (i,j) index table; coef streamed in 16KB chunks.
// ============================================================================
// dyn smem layout (bytes):
//  s1f : 0       [128][66] f     33,792
//  w1s : 33792   [128][66] f     33,792
//  w2t : 67584   [128][66] f     33,792   (W2 transposed: [f][c])
//  UN  : 101376  phaseA { zse [128][65] f (33,280) ; ta u8x2 @+33,280 (4,352) ;
//                         cch [64][64] f @+37,632 (16,384) }
//                phaseC { h1s [128][129] f (66,048) }
//  par : 167424  448 floats: g1,b1n,g2,b2n (64 ea), bf1(128), bf2(64)  1,792
#define SINDY_SMEM 169216

__global__ __launch_bounds__(256, 1) void k_sindy(int layer, float* __restrict__ out_ext,
                                                  const float* __restrict__ coef,
                                                  const float* __restrict__ g1,
                                                  const float* __restrict__ b1n,
                                                  const float* __restrict__ W1,
                                                  const float* __restrict__ bf1,
                                                  const float* __restrict__ W2,
                                                  const float* __restrict__ bf2,
                                                  const float* __restrict__ g2,
                                                  const float* __restrict__ b2n) {
    extern __shared__ char sm[];
    float* s1f = (float*)sm;                       // [128][66]
    float* w1s = (float*)(sm + 33792);             // [128][66]
    float* w2t = (float*)(sm + 67584);             // [128][66]
    char*  un  = sm + 101376;
    float* zse = (float*)un;                       // [128][65]
    unsigned char* ta = (unsigned char*)(un + 33280);
    float* cch = (float*)(un + 37632);             // [64][64]
    float* h1s = (float*)un;                       // [128][129] (phase C)
    float* par = (float*)(sm + 167424);

    const float* in = (layer == 0) ? g_bufA : g_bufB;
    float* outp     = (layer == 0) ? g_bufB : out_ext;
    float* tail     = out_ext + NROW * HID;
    const int final_layer = (layer == 1);

    const int t = threadIdx.x;
    const int r = t >> 1;
    const int p = t & 1;
    const int row0 = blockIdx.x * 128;

    // ---- load z tile (+1.0 column), params, W1, W2^T ----
    const float* inb = in + (size_t)row0 * HID;
    for (int idx = t; idx < 128 * 64; idx += 256)
        zse[(idx >> 6) * 65 + (idx & 63)] = inb[idx];
    if (t < 128) zse[t * 65 + 64] = 1.0f;

    for (int idx = t; idx < 448; idx += 256) {
        float v;
        if      (idx < 64)  v = g1[idx];
        else if (idx < 128) v = b1n[idx - 64];
        else if (idx < 192) v = g2[idx - 128];
        else if (idx < 256) v = b2n[idx - 192];
        else if (idx < 384) v = bf1[idx - 256];
        else                v = bf2[idx - 384];
        par[idx] = v;
    }
    for (int idx = t; idx < 128 * 64; idx += 256) {
        int f = idx >> 6, c = idx & 63;
        w1s[f * 66 + c] = W1[idx];
    }
    for (int idx = t; idx < 64 * 128; idx += 256) {
        int c = idx >> 7, f = idx & 127;
        w2t[f * 66 + c] = W2[idx];
    }

    // ---- (i,j) index table: term k -> zse[i]*zse[j]; col 64 == 1.0 ----
    for (int k = t; k < NLIB; k += 256) {
        int i, j;
        if (k == 0)      { i = 64; j = 64; }
        else if (k < 65) { i = k - 1; j = 64; }
        else {
            int q = k - 65;
            i = (int)floorf((129.0f - sqrtf(16641.0f - 8.0f * (float)q)) * 0.5f);
            if (i < 0) i = 0; if (i > 63) i = 63;
            while (i < 63 && ((i + 1) * 64 - (i + 1) * i / 2) <= q) i++;
            while (i > 0 && (i * 64 - i * (i - 1) / 2) > q) i--;
            j = i + (q - (i * 64 - i * (i - 1) / 2));
        }
        ta[2 * k]     = (unsigned char)i;
        ta[2 * k + 1] = (unsigned char)j;
    }
    __syncthreads();

    // ---- phase A: upd = Theta @ coef (on-the-fly Theta) ----
    u64 acc[16];
#pragma unroll
    for (int u = 0; u < 16; u++) acc[u] = 0ull;
    const float* zr = zse + r * 65;

    for (int kb = 0; kb < NLIB; kb += 64) {
        const int klen = (NLIB - kb < 64) ? (NLIB - kb) : 64;
        __syncthreads();  // previous chunk fully consumed
        const float4* src4 = (const float4*)(coef + (size_t)kb * 64);
        float4* dst4 = (float4*)cch;
        for (int idx = t; idx < klen * 16; idx += 256) dst4[idx] = src4[idx];
        __syncthreads();  // chunk ready

        const u64* crow = (const u64*)cch + p * 16;
        for (int kk = 0; kk < klen; kk++) {
            unsigned short uv = *(const unsigned short*)(ta + 2 * (kb + kk));
            float a = zr[uv & 255] * zr[uv >> 8];
            u64 a2 = bcast2(a);
            const u64* c = crow + kk * 32;
#pragma unroll
            for (int u = 0; u < 16; u++) acc[u] = fma2(a2, c[u], acc[u]);
        }
    }

    // ---- phase B: residual + LN1 -> s1f ----
#pragma unroll
    for (int u = 0; u < 16; u++) {
        float x0, x1; unpack2(acc[u], x0, x1);
        int c = p * 32 + 2 * u;
        s1f[r * 66 + c]     = zr[c] + x0;
        s1f[r * 66 + c + 1] = zr[c + 1] + x1;
    }
    __syncthreads();
    if (t < 128) {
        float* rowp = s1f + t * 66;
        float s = 0.0f, s2 = 0.0f;
        for (int c = 0; c < 64; c++) { float v = rowp[c]; s += v; s2 += v * v; }
        float m = s * (1.0f / 64.0f);
        float inv = rsqrtf(s2 * (1.0f / 64.0f) - m * m + 1e-5f);
        for (int c = 0; c < 64; c++)
            rowp[c] = (rowp[c] - m) * inv * par[c] + par[64 + c];
    }
    __syncthreads();

    // ---- phase C1: FF1 -> gelu -> h1s ----
    {
        u64 s1r[32];
        const u64* srow = (const u64*)(s1f + r * 66);
#pragma unroll
        for (int cc = 0; cc < 32; cc++) s1r[cc] = srow[cc];
        for (int f0 = 0; f0 < 64; f0++) {
            int f = p * 64 + f0;
            u64 a = 0ull;
            const u64* wrow = (const u64*)(w1s + f * 66);
#pragma unroll
            for (int cc = 0; cc < 32; cc++) a = fma2(s1r[cc], wrow[cc], a);
            float v = hadd2(a) + par[256 + f];
            h1s[r * 129 + f] = 0.5f * v * (1.0f + erff(v * 0.70710678118654752f));
        }
    }
    __syncthreads();

    // ---- phase C2: FF2 + residual + LN2 (register LN via shfl partner) ----
    {
        u64 acc3[16];
#pragma unroll
        for (int u = 0; u < 16; u++) {
            int c = p * 32 + 2 * u;
            acc3[u] = pack2(s1f[r * 66 + c] + par[384 + c],
                            s1f[r * 66 + c + 1] + par[384 + c + 1]);
        }
        const float* hrow = h1s + r * 129;
        for (int f = 0; f < 128; f++) {
            u64 a2 = bcast2(hrow[f]);
            const u64* wrow = (const u64*)(w2t + f * 66) + p * 16;
#pragma unroll
            for (int u = 0; u < 16; u++) acc3[u] = fma2(a2, wrow[u], acc3[u]);
        }
        float vals[32];
        float s = 0.0f, s2 = 0.0f;
#pragma unroll
        for (int u = 0; u < 16; u++) {
            float x0, x1; unpack2(acc3[u], x0, x1);
            vals[2 * u] = x0; vals[2 * u + 1] = x1;
            s += x0 + x1; s2 += x0 * x0 + x1 * x1;
        }
        s  += __shfl_xor_sync(0xffffffffu, s, 1);
        s2 += __shfl_xor_sync(0xffffffffu, s2, 1);
        float m = s * (1.0f / 64.0f);
        float inv = rsqrtf(s2 * (1.0f / 64.0f) - m * m + 1e-5f);
#pragma unroll
        for (int u = 0; u < 32; u++)
            vals[u] = (vals[u] - m) * inv * par[128 + p * 32 + u] + par[192 + p * 32 + u];

        const int grow = row0 + r;
        float2* op2 = (float2*)(outp + (size_t)grow * HID + p * 32);
#pragma unroll
        for (int u = 0; u < 16; u++) op2[u] = make_float2(vals[2 * u], vals[2 * u + 1]);

        if (final_layer && (grow % SEQ) == (SEQ - 1)) {
            float* tp = tail + (grow / SEQ) * HID + p * 32;
#pragma unroll
            for (int u = 0; u < 32; u++) tp[u] = vals[u];
        }
    }
}

// ============================================================================
extern "C" void kernel_launch(void* const* d_in, const int* in_sizes, int n_in,
                              void* d_out, int out_size) {
    const float* x     = (const float*)d_in[0];
    const float* Wih0  = (const float*)d_in[1];
    const float* Whh0  = (const float*)d_in[2];
    const float* bih0  = (const float*)d_in[3];
    const float* bhh0  = (const float*)d_in[4];
    const float* Wih1  = (const float*)d_in[5];
    const float* Whh1  = (const float*)d_in[6];
    const float* bih1  = (const float*)d_in[7];
    const float* bhh1  = (const float*)d_in[8];
    const float* coeffs= (const float*)d_in[9];
    const float* ln1_g = (const float*)d_in[10];
    const float* ln1_b = (const float*)d_in[11];
    const float* W1    = (const float*)d_in[12];
    const float* b1    = (const float*)d_in[13];
    const float* W2    = (const float*)d_in[14];
    const float* b2    = (const float*)d_in[15];
    const float* ln2_g = (const float*)d_in[16];
    const float* ln2_b = (const float*)d_in[17];
    float* out = (float*)d_out;

    cudaFuncSetAttribute(k_gru,   cudaFuncAttributeMaxDynamicSharedMemorySize, GRU_SMEM);
    cudaFuncSetAttribute(k_sindy, cudaFuncAttributeMaxDynamicSharedMemorySize, SINDY_SMEM);

    k_xp0<<<500, 192>>>(x, Wih0, bih0);
    k_gru<<<32, 192, GRU_SMEM>>>(Whh0, Wih1, Whh1, bhh0, bih1, bhh1);

    for (int l = 0; l < 2; l++) {
        k_sindy<<<125, 256, SINDY_SMEM>>>(l, out,
            coeffs + (size_t)l * NLIB * HID,
            ln1_g + l * HID, ln1_b + l * HID,
            W1 + (size_t)l * FFD * HID, b1 + l * FFD,
            W2 + (size_t)l * HID * FFD, b2 + l * HID,
            ln2_g + l * HID, ln2_b + l * HID);
    }
}

// round 6
// speedup vs baseline: 2.6304x; 2.6304x over previous
#include <cuda_runtime.h>

typedef unsigned long long u64;

#define BATCH 32
#define SEQ   500
#define DM    128
#define HID   64
#define G3    192        // 3*HID
#define NROW  16000      // BATCH*SEQ
#define NLIB  2145
#define FFD   128
#define NCH   34         // ceil(2145/64)

// ---------------- scratch (device globals; no allocation allowed) ----------
__device__ float g_xp0[BATCH * SEQ * G3];    // input projections for GRU L0
__device__ float g_bufA[NROW * HID];         // GRU output
__device__ float g_bufB[NROW * HID];         // SINDy layer 0 output

// ---------------- packed f32x2 helpers ------------------------------------
__device__ __forceinline__ u64 fma2(u64 a, u64 b, u64 c) {
    u64 d; asm("fma.rn.f32x2 %0, %1, %2, %3;" : "=l"(d) : "l"(a), "l"(b), "l"(c)); return d;
}
__device__ __forceinline__ u64 pack2(float x, float y) {
    u64 r; asm("mov.b64 %0, {%1, %2};" : "=l"(r) : "f"(x), "f"(y)); return r;
}
__device__ __forceinline__ u64 bcast2(float x) {
    u64 r; asm("mov.b64 %0, {%1, %1};" : "=l"(r) : "f"(x)); return r;
}
__device__ __forceinline__ void unpack2(u64 v, float& x, float& y) {
    asm("mov.b64 {%0, %1}, %2;" : "=f"(x), "=f"(y) : "l"(v));
}
__device__ __forceinline__ float hadd2(u64 v) { float x, y; unpack2(v, x, y); return x + y; }

__device__ __forceinline__ float sigf(float v) { return 1.0f / (1.0f + __expf(-v)); }

// ============================================================================
// K1: g_xp0[row][g] = bih0[g] + sum_k x[row][k] * Wih0[g][k]
// ============================================================================
__global__ __launch_bounds__(192) void k_xp0(const float* __restrict__ x,
                                             const float* __restrict__ Wih0,
                                             const float* __restrict__ bih0) {
    __shared__ u64 xs[32 * 64];
    const int g = threadIdx.x;
    const u64* x2 = (const u64*)x + (size_t)blockIdx.x * 2048;
    for (int idx = g; idx < 2048; idx += 192) xs[idx] = x2[idx];
    __syncthreads();

    const u64* wp = (const u64*)Wih0 + (size_t)g * 64;
    u64 acc[32];
#pragma unroll
    for (int r = 0; r < 32; r++) acc[r] = 0ull;

    for (int kk = 0; kk < 64; kk++) {
        u64 w = __ldg(&wp[kk]);
#pragma unroll
        for (int r = 0; r < 32; r++) acc[r] = fma2(w, xs[r * 64 + kk], acc[r]);
    }
    const float bias = bih0[g];
    const int row0 = blockIdx.x * 32;
#pragma unroll
    for (int r = 0; r < 32; r++)
        g_xp0[(size_t)(row0 + r) * G3 + g] = hadd2(acc[r]) + bias;
}

// ============================================================================
// K2: software-pipelined 2-layer GRU. 32 blocks x 384 threads.
//   warps 0-3  (t<128) : layer 0, thread (j = t>>1, sub = t&1 -> half of K)
//   warps 4-11 (t>=128): layer 1, thread (j = (t-128)>>2, sub = &3 -> quarter K)
// At iteration s: L0 computes h0[s], L1 computes h1[s-1]. One barrier/step.
// Weights register-resident. Gate rows j, j+64, j+128 all in the same thread;
// K-dim partial sums recombined with shfl_xor -> no matvec->gate barrier.
// ============================================================================
__global__ __launch_bounds__(384, 1) void k_gru(const float* __restrict__ Whh0,
                                                const float* __restrict__ Wih1,
                                                const float* __restrict__ Whh1,
                                                const float* __restrict__ bhh0,
                                                const float* __restrict__ bih1,
                                                const float* __restrict__ bhh1) {
    __shared__ float h0buf[2 * 64];
    __shared__ float h1buf[2 * 64];

    const int t = threadIdx.x;
    const int b = blockIdx.x;
    const float* xp = g_xp0 + (size_t)b * SEQ * G3;
    float* outp = g_bufA + (size_t)b * SEQ * HID;

    u64 w[48];
    float b3[3];
    float b4 = 0.0f;           // L1 only: bhh1 for n-gate (kept separate from bih1)
    float hreg = 0.0f;
    float xc0 = 0, xc1 = 0, xc2 = 0;
    int j, sub;

    if (t < 128) {
        j = t >> 1; sub = t & 1;
        const u64* W0 = (const u64*)Whh0;
#pragma unroll
        for (int g = 0; g < 3; g++) {
#pragma unroll
            for (int k = 0; k < 16; k++)
                w[g * 16 + k] = __ldg(&W0[(size_t)(j + 64 * g) * 32 + sub * 16 + k]);
            b3[g] = bhh0[j + 64 * g];
        }
        xc0 = xp[j]; xc1 = xp[64 + j]; xc2 = xp[128 + j];
        if (t < 64) { h0buf[64 + t] = 0.0f; h1buf[t] = 0.0f; }
    } else {
        const int tt = t - 128;
        j = tt >> 2; sub = tt & 3;
        const u64* Wi = (const u64*)Wih1;
        const u64* Wh = (const u64*)Whh1;
#pragma unroll
        for (int g = 0; g < 3; g++) {
#pragma unroll
            for (int k = 0; k < 8; k++) {
                w[g * 16 + k]     = __ldg(&Wi[(size_t)(j + 64 * g) * 32 + sub * 8 + k]);
                w[g * 16 + 8 + k] = __ldg(&Wh[(size_t)(j + 64 * g) * 32 + sub * 8 + k]);
            }
        }
        b3[0] = bih1[j] + bhh1[j];
        b3[1] = bih1[j + 64] + bhh1[j + 64];
        b3[2] = bih1[j + 128];
        b4    = bhh1[j + 128];
    }
    __syncthreads();

    for (int s = 0; s <= SEQ; s++) {
        if (t < 128) {
            if (s < SEQ) {
                float xn0 = 0, xn1 = 0, xn2 = 0;
                if (s + 1 < SEQ) {   // prefetch next step's input projections
                    const float* xr = xp + (size_t)(s + 1) * G3;
                    xn0 = xr[j]; xn1 = xr[64 + j]; xn2 = xr[128 + j];
                }
                const u64* hb = (const u64*)(h0buf + ((s & 1) ^ 1) * 64) + sub * 16;
                u64 a0 = 0, a1 = 0, a2 = 0;
#pragma unroll
                for (int k = 0; k < 16; k++) {
                    u64 hv = hb[k];
                    a0 = fma2(w[k], hv, a0);
                    a1 = fma2(w[16 + k], hv, a1);
                    a2 = fma2(w[32 + k], hv, a2);
                }
                float d0 = hadd2(a0), d1 = hadd2(a1), d2 = hadd2(a2);
                d0 += __shfl_xor_sync(0xffffffffu, d0, 1);
                d1 += __shfl_xor_sync(0xffffffffu, d1, 1);
                d2 += __shfl_xor_sync(0xffffffffu, d2, 1);
                float rg = sigf(xc0 + d0 + b3[0]);
                float zg = sigf(xc1 + d1 + b3[1]);
                float ng = tanhf(xc2 + rg * (d2 + b3[2]));
                hreg = (1.0f - zg) * ng + zg * hreg;
                if (sub == 0) h0buf[(s & 1) * 64 + j] = hreg;
                xc0 = xn0; xc1 = xn1; xc2 = xn2;
            }
        } else {
            if (s >= 1) {
                const int sl = (s & 1) ^ 1;
                const u64* hb0 = (const u64*)(h0buf + sl * 64) + sub * 8;
                const u64* hb1 = (const u64*)(h1buf + sl * 64) + sub * 8;
                u64 a0 = 0, a1 = 0, a2i = 0, a2h = 0;
#pragma unroll
                for (int k = 0; k < 8; k++) {
                    u64 h0v = hb0[k], h1v = hb1[k];
                    a0  = fma2(w[k],      h0v, a0);
                    a0  = fma2(w[8 + k],  h1v, a0);
                    a1  = fma2(w[16 + k], h0v, a1);
                    a1  = fma2(w[24 + k], h1v, a1);
                    a2i = fma2(w[32 + k], h0v, a2i);
                    a2h = fma2(w[40 + k], h1v, a2h);
                }
                float d0 = hadd2(a0), d1 = hadd2(a1);
                float di = hadd2(a2i), dh = hadd2(a2h);
                d0 += __shfl_xor_sync(0xffffffffu, d0, 1);
                d1 += __shfl_xor_sync(0xffffffffu, d1, 1);
                di += __shfl_xor_sync(0xffffffffu, di, 1);
                dh += __shfl_xor_sync(0xffffffffu, dh, 1);
                d0 += __shfl_xor_sync(0xffffffffu, d0, 2);
                d1 += __shfl_xor_sync(0xffffffffu, d1, 2);
                di += __shfl_xor_sync(0xffffffffu, di, 2);
                dh += __shfl_xor_sync(0xffffffffu, dh, 2);
                float rg = sigf(d0 + b3[0]);
                float zg = sigf(d1 + b3[1]);
                float ng = tanhf(di + b3[2] + rg * (dh + b4));
                hreg = (1.0f - zg) * ng + zg * hreg;
                if (sub == 0) {
                    h1buf[(s & 1) * 64 + j] = hreg;
                    outp[(size_t)(s - 1) * HID + j] = hreg;
                }
            }
        }
        __syncthreads();
    }
}

// ============================================================================
// K3: fused SINDy layer. 125 blocks x 256 threads.
// Phase A: register-tiled smem GEMM (8 rows x 4 cols per thread), Theta chunks
// pre-materialized per 64-K block from transposed z; double-buffered Theta/coef.
// ----------------------------------------------------------------------------
// dyn smem (bytes):
//  A: zT  @0       [65][132] f   34,320   (row 64 == 1.0 column)
//     th0 @34,320  [64][132] f   33,792
//     th1 @68,112  [64][132] f   33,792
//     cc0 @101,904 [64][64]  f   16,384
//     cc1 @118,288 [64][64]  f   16,384
//     ta  @134,672 u8 x 2 x 2145  4,352
//  C: s1f @0       [128][66] f   33,792
//     w1s @33,792  [128][66] f   33,792
//     w2t @67,584  [128][66] f   33,792
//     h1s @101,376 [128][129] f  66,048
//  par   @167,424  448 f          1,792
#define SINDY_SMEM 169216

__global__ __launch_bounds__(256, 1) void k_sindy(int layer, float* __restrict__ out_ext,
                                                  const float* __restrict__ coef,
                                                  const float* __restrict__ g1,
                                                  const float* __restrict__ b1n,
                                                  const float* __restrict__ W1,
                                                  const float* __restrict__ bf1,
                                                  const float* __restrict__ W2,
                                                  const float* __restrict__ bf2,
                                                  const float* __restrict__ g2,
                                                  const float* __restrict__ b2n) {
    extern __shared__ char sm[];
    float* zT  = (float*)sm;                        // [65][132]
    float* th0 = (float*)(sm + 34320);
    float* th1 = (float*)(sm + 68112);
    float* cc0 = (float*)(sm + 101904);
    float* cc1 = (float*)(sm + 118288);
    unsigned char* ta = (unsigned char*)(sm + 134672);
    float* s1f = (float*)sm;                        // [128][66] (phase C)
    float* w1s = (float*)(sm + 33792);
    float* w2t = (float*)(sm + 67584);
    float* h1s = (float*)(sm + 101376);             // [128][129]
    float* par = (float*)(sm + 167424);

    const float* in = (layer == 0) ? g_bufA : g_bufB;
    float* outp     = (layer == 0) ? g_bufB : out_ext;
    float* tail     = out_ext + NROW * HID;
    const int final_layer = (layer == 1);

    const int t = threadIdx.x;
    const int row0 = blockIdx.x * 128;

    // ---- load z transposed (+ ones row 64), params, index table ----
    const float* inb = in + (size_t)row0 * HID;
    for (int idx = t; idx < 128 * 64; idx += 256) {
        int r = idx >> 6, c = idx & 63;
        zT[c * 132 + r] = inb[idx];
    }
    if (t < 128) zT[64 * 132 + t] = 1.0f;

    for (int idx = t; idx < 448; idx += 256) {
        float v;
        if      (idx < 64)  v = g1[idx];
        else if (idx < 128) v = b1n[idx - 64];
        else if (idx < 192) v = g2[idx - 128];
        else if (idx < 256) v = b2n[idx - 192];
        else if (idx < 384) v = bf1[idx - 256];
        else                v = bf2[idx - 384];
        par[idx] = v;
    }

    for (int k = t; k < NLIB; k += 256) {
        int i, j;
        if (k == 0)      { i = 64; j = 64; }
        else if (k < 65) { i = k - 1; j = 64; }
        else {
            int q = k - 65;
            i = (int)floorf((129.0f - sqrtf(16641.0f - 8.0f * (float)q)) * 0.5f);
            if (i < 0) i = 0; if (i > 63) i = 63;
            while (i < 63 && ((i + 1) * 64 - (i + 1) * i / 2) <= q) i++;
            while (i > 0 && (i * 64 - i * (i - 1) / 2) > q) i--;
            j = i + (q - (i * 64 - i * (i - 1) / 2));
        }
        ta[2 * k]     = (unsigned char)i;
        ta[2 * k + 1] = (unsigned char)j;
    }
    __syncthreads();

    // ---- phase A: upd = Theta @ coef, register-tiled, double-buffered ----
    const int tx = t & 15, ty = t >> 4;
    const int c0 = tx * 4, r0 = ty * 8;

    u64 acc[16];    // acc[rp*4 + jc]: rows (r0+2rp, r0+2rp+1), col c0+jc
#pragma unroll
    for (int u = 0; u < 16; u++) acc[u] = 0ull;

    // prologue: stage chunk 0
    {
        const float4* src4 = (const float4*)coef;
        float4* dst4 = (float4*)cc0;
#pragma unroll
        for (int ii = 0; ii < 4; ii++) dst4[t + ii * 256] = src4[t + ii * 256];
#pragma unroll
        for (int ii = 0; ii < 8; ii++) {
            int idx = t + ii * 256;
            int kk = idx >> 5, rq = idx & 31;
            int i = ta[2 * kk], j = ta[2 * kk + 1];
            float4 zi = *(const float4*)(zT + i * 132 + rq * 4);
            float4 zj = *(const float4*)(zT + j * 132 + rq * 4);
            float4 o = make_float4(zi.x * zj.x, zi.y * zj.y, zi.z * zj.z, zi.w * zj.w);
            *(float4*)(th0 + kk * 132 + rq * 4) = o;
        }
    }
    __syncthreads();

    for (int cn = 0; cn < NCH; cn++) {
        const float* thc = (cn & 1) ? th1 : th0;
        const float* ccc = (cn & 1) ? cc1 : cc0;
        float* thn = (cn & 1) ? th0 : th1;
        float* ccn = (cn & 1) ? cc0 : cc1;
        const int kb_n = (cn + 1) * 64;
        const int klen_n = (kb_n < NLIB) ? ((NLIB - kb_n < 64) ? (NLIB - kb_n) : 64) : 0;
        const int klen   = (NLIB - cn * 64 < 64) ? (NLIB - cn * 64) : 64;

        // prefetch next coef chunk into registers (overlaps with fma loop)
        float4 cr[4];
        if (klen_n > 0) {
            const float4* src4 = (const float4*)(coef + (size_t)kb_n * 64);
            const int lim = klen_n * 16;
#pragma unroll
            for (int ii = 0; ii < 4; ii++) {
                int idx = t + ii * 256;
                if (idx < lim) cr[ii] = src4[idx];
            }
        }

        // main fma loop over this chunk
#pragma unroll 4
        for (int kk = 0; kk < klen; kk++) {
            ulonglong2 q0 = *(const ulonglong2*)(thc + kk * 132 + r0);      // rows r0..r0+3
            ulonglong2 q1 = *(const ulonglong2*)(thc + kk * 132 + r0 + 4);  // rows r0+4..r0+7
            float4 cf = *(const float4*)(ccc + kk * 64 + c0);
            u64 b0 = bcast2(cf.x), b1 = bcast2(cf.y), b2 = bcast2(cf.z), b3 = bcast2(cf.w);
            acc[0]  = fma2(q0.x, b0, acc[0]);  acc[1]  = fma2(q0.x, b1, acc[1]);
            acc[2]  = fma2(q0.x, b2, acc[2]);  acc[3]  = fma2(q0.x, b3, acc[3]);
            acc[4]  = fma2(q0.y, b0, acc[4]);  acc[5]  = fma2(q0.y, b1, acc[5]);
            acc[6]  = fma2(q0.y, b2, acc[6]);  acc[7]  = fma2(q0.y, b3, acc[7]);
            acc[8]  = fma2(q1.x, b0, acc[8]);  acc[9]  = fma2(q1.x, b1, acc[9]);
            acc[10] = fma2(q1.x, b2, acc[10]); acc[11] = fma2(q1.x, b3, acc[11]);
            acc[12] = fma2(q1.y, b0, acc[12]); acc[13] = fma2(q1.y, b1, acc[13]);
            acc[14] = fma2(q1.y, b2, acc[14]); acc[15] = fma2(q1.y, b3, acc[15]);
        }

        // stage next chunk (coef STS + theta build) into the other buffer
        if (klen_n > 0) {
            float4* dst4 = (float4*)ccn;
            const int lim = klen_n * 16;
#pragma unroll
            for (int ii = 0; ii < 4; ii++) {
                int idx = t + ii * 256;
                if (idx < lim) dst4[idx] = cr[ii];
            }
#pragma unroll
            for (int ii = 0; ii < 8; ii++) {
                int idx = t + ii * 256;
                int kk = idx >> 5, rq = idx & 31;
                if (kk < klen_n) {
                    int i = ta[2 * (kb_n + kk)], j = ta[2 * (kb_n + kk) + 1];
                    float4 zi = *(const float4*)(zT + i * 132 + rq * 4);
                    float4 zj = *(const float4*)(zT + j * 132 + rq * 4);
                    float4 o = make_float4(zi.x * zj.x, zi.y * zj.y, zi.z * zj.z, zi.w * zj.w);
                    *(float4*)(thn + kk * 132 + rq * 4) = o;
                }
            }
        }
        __syncthreads();
    }

    // ---- phase B: residual (read zT into regs), then write s1f (aliases zT) ----
    float vals[32];   // vals[rr*4 + jc] = row r0+rr, col c0+jc
#pragma unroll
    for (int rp = 0; rp < 4; rp++)
#pragma unroll
        for (int jc = 0; jc < 4; jc++) {
            float v0, v1; unpack2(acc[rp * 4 + jc], v0, v1);
            vals[(2 * rp) * 4 + jc]     = v0 + zT[(c0 + jc) * 132 + r0 + 2 * rp];
            vals[(2 * rp + 1) * 4 + jc] = v1 + zT[(c0 + jc) * 132 + r0 + 2 * rp + 1];
        }
    __syncthreads();
#pragma unroll
    for (int rr = 0; rr < 8; rr++)
#pragma unroll
        for (int jc = 0; jc < 4; jc++)
            s1f[(r0 + rr) * 66 + c0 + jc] = vals[rr * 4 + jc];
    __syncthreads();

    // LN1 (half the threads) runs while the others stage W1 / W2^T
    if (t < 128) {
        float* rowp = s1f + t * 66;
        float s = 0.0f, s2 = 0.0f;
        for (int c = 0; c < 64; c++) { float v = rowp[c]; s += v; s2 += v * v; }
        float m = s * (1.0f / 64.0f);
        float inv = rsqrtf(s2 * (1.0f / 64.0f) - m * m + 1e-5f);
        for (int c = 0; c < 64; c++)
            rowp[c] = (rowp[c] - m) * inv * par[c] + par[64 + c];
    } else {
        const int t2 = t - 128;
        for (int idx = t2; idx < 128 * 64; idx += 128) {
            int f = idx >> 6, c = idx & 63;
            w1s[f * 66 + c] = W1[idx];
        }
        for (int idx = t2; idx < 64 * 128; idx += 128) {
            int c = idx >> 7, f = idx & 127;
            w2t[f * 66 + c] = W2[idx];
        }
    }
    __syncthreads();

    // ---- phase C1: FF1 -> gelu -> h1s ----
    const int r = t >> 1;
    const int p = t & 1;
    {
        u64 s1r[32];
        const u64* srow = (const u64*)(s1f + r * 66);
#pragma unroll
        for (int cc = 0; cc < 32; cc++) s1r[cc] = srow[cc];
        for (int f0 = 0; f0 < 64; f0++) {
            int f = p * 64 + f0;
            u64 a = 0ull;
            const u64* wrow = (const u64*)(w1s + f * 66);
#pragma unroll
            for (int cc = 0; cc < 32; cc++) a = fma2(s1r[cc], wrow[cc], a);
            float v = hadd2(a) + par[256 + f];
            h1s[r * 129 + f] = 0.5f * v * (1.0f + erff(v * 0.70710678118654752f));
        }
    }
    __syncthreads();

    // ---- phase C2: FF2 + residual + LN2 (register LN via shfl partner) ----
    {
        u64 acc3[16];
#pragma unroll
        for (int u = 0; u < 16; u++) {
            int c = p * 32 + 2 * u;
            acc3[u] = pack2(s1f[r * 66 + c] + par[384 + c],
                            s1f[r * 66 + c + 1] + par[384 + c + 1]);
        }
        const float* hrow = h1s + r * 129;
        for (int f = 0; f < 128; f++) {
            u64 a2 = bcast2(hrow[f]);
            const u64* wrow = (const u64*)(w2t + f * 66) + p * 16;
#pragma unroll
            for (int u = 0; u < 16; u++) acc3[u] = fma2(a2, wrow[u], acc3[u]);
        }
        float ov[32];
        float s = 0.0f, s2 = 0.0f;
#pragma unroll
        for (int u = 0; u < 16; u++) {
            float x0, x1; unpack2(acc3[u], x0, x1);
            ov[2 * u] = x0; ov[2 * u + 1] = x1;
            s += x0 + x1; s2 += x0 * x0 + x1 * x1;
        }
        s  += __shfl_xor_sync(0xffffffffu, s, 1);
        s2 += __shfl_xor_sync(0xffffffffu, s2, 1);
        float m = s * (1.0f / 64.0f);
        float inv = rsqrtf(s2 * (1.0f / 64.0f) - m * m + 1e-5f);
#pragma unroll
        for (int u = 0; u < 32; u++)
            ov[u] = (ov[u] - m) * inv * par[128 + p * 32 + u] + par[192 + p * 32 + u];

        const int grow = row0 + r;
        float2* op2 = (float2*)(outp + (size_t)grow * HID + p * 32);
#pragma unroll
        for (int u = 0; u < 16; u++) op2[u] = make_float2(ov[2 * u], ov[2 * u + 1]);

        if (final_layer && (grow % SEQ) == (SEQ - 1)) {
            float* tp = tail + (grow / SEQ) * HID + p * 32;
#pragma unroll
            for (int u = 0; u < 32; u++) tp[u] = ov[u];
        }
    }
}

// ============================================================================
extern "C" void kernel_launch(void* const* d_in, const int* in_sizes, int n_in,
                              void* d_out, int out_size) {
    const float* x     = (const float*)d_in[0];
    const float* Wih0  = (const float*)d_in[1];
    const float* Whh0  = (const float*)d_in[2];
    const float* bih0  = (const float*)d_in[3];
    const float* bhh0  = (const float*)d_in[4];
    const float* Wih1  = (const float*)d_in[5];
    const float* Whh1  = (const float*)d_in[6];
    const float* bih1  = (const float*)d_in[7];
    const float* bhh1  = (const float*)d_in[8];
    const float* coeffs= (const float*)d_in[9];
    const float* ln1_g = (const float*)d_in[10];
    const float* ln1_b = (const float*)d_in[11];
    const float* W1    = (const float*)d_in[12];
    const float* b1    = (const float*)d_in[13];
    const float* W2    = (const float*)d_in[14];
    const float* b2    = (const float*)d_in[15];
    const float* ln2_g = (const float*)d_in[16];
    const float* ln2_b = (const float*)d_in[17];
    float* out = (float*)d_out;

    cudaFuncSetAttribute(k_sindy, cudaFuncAttributeMaxDynamicSharedMemorySize, SINDY_SMEM);

    k_xp0<<<500, 192>>>(x, Wih0, bih0);
    k_gru<<<32, 384>>>(Whh0, Wih1, Whh1, bhh0, bih1, bhh1);

    for (int l = 0; l < 2; l++) {
        k_sindy<<<125, 256, SINDY_SMEM>>>(l, out,
            coeffs + (size_t)l * NLIB * HID,
            ln1_g + l * HID, ln1_b + l * HID,
            W1 + (size_t)l * FFD * HID, b1 + l * FFD,
            W2 + (size_t)l * HID * FFD, b2 + l * HID,
            ln2_g + l * HID, ln2_b + l * HID);
    }
}

// round 7
// speedup vs baseline: 3.0170x; 1.1470x over previous
#include <cuda_runtime.h>

typedef unsigned long long u64;

#define BATCH 32
#define SEQ   500
#define DM    128
#define HID   64
#define G3    192        // 3*HID
#define NROW  16000      // BATCH*SEQ
#define NLIB  2145
#define FFD   128
#define NCH   34         // ceil(2145/64)

// ---------------- scratch (device globals; no allocation allowed) ----------
__device__ float g_xp0[BATCH * SEQ * G3];    // input projections for GRU L0
__device__ float g_bufA[NROW * HID];         // GRU output
__device__ float g_bufB[NROW * HID];         // SINDy layer 0 output

// ---------------- packed f32x2 helpers ------------------------------------
__device__ __forceinline__ u64 fma2(u64 a, u64 b, u64 c) {
    u64 d; asm("fma.rn.f32x2 %0, %1, %2, %3;" : "=l"(d) : "l"(a), "l"(b), "l"(c)); return d;
}
__device__ __forceinline__ u64 add2(u64 a, u64 b) {
    u64 d; asm("add.rn.f32x2 %0, %1, %2;" : "=l"(d) : "l"(a), "l"(b)); return d;
}
__device__ __forceinline__ u64 mul2(u64 a, u64 b) {
    u64 d; asm("mul.rn.f32x2 %0, %1, %2;" : "=l"(d) : "l"(a), "l"(b)); return d;
}
__device__ __forceinline__ u64 pack2(float x, float y) {
    u64 r; asm("mov.b64 %0, {%1, %2};" : "=l"(r) : "f"(x), "f"(y)); return r;
}
__device__ __forceinline__ u64 bcast2(float x) {
    u64 r; asm("mov.b64 %0, {%1, %1};" : "=l"(r) : "f"(x)); return r;
}
__device__ __forceinline__ void unpack2(u64 v, float& x, float& y) {
    asm("mov.b64 {%0, %1}, %2;" : "=f"(x), "=f"(y) : "l"(v));
}
__device__ __forceinline__ float hadd2(u64 v) { float x, y; unpack2(v, x, y); return x + y; }

// fast activations: ex2.approx (rel err ~2^-22) + rcp.approx (1 ulp) -> ~1e-6
__device__ __forceinline__ float fast_rcp(float x) {
    float r; asm("rcp.approx.f32 %0, %1;" : "=f"(r) : "f"(x)); return r;
}
__device__ __forceinline__ float fast_ex2(float x) {
    float r; asm("ex2.approx.f32 %0, %1;" : "=f"(r) : "f"(x)); return r;
}
__device__ __forceinline__ float sigf(float v) {
    return fast_rcp(1.0f + fast_ex2(-1.4426950408889634f * v));
}
__device__ __forceinline__ float tanh_fast(float v) {
    // tanh(x) = 1 - 2/(exp(2x)+1); exp(2x) = 2^(2.885390x)
    float e = fast_ex2(2.8853900817779268f * v);
    return 1.0f - 2.0f * fast_rcp(e + 1.0f);
}

// ============================================================================
// K1: g_xp0[row][g] = bih0[g] + sum_k x[row][k] * Wih0[g][k]
// ============================================================================
__global__ __launch_bounds__(192) void k_xp0(const float* __restrict__ x,
                                             const float* __restrict__ Wih0,
                                             const float* __restrict__ bih0) {
    __shared__ u64 xs[32 * 64];
    const int g = threadIdx.x;
    const u64* x2 = (const u64*)x + (size_t)blockIdx.x * 2048;
    for (int idx = g; idx < 2048; idx += 192) xs[idx] = x2[idx];
    __syncthreads();

    const u64* wp = (const u64*)Wih0 + (size_t)g * 64;
    u64 acc[32];
#pragma unroll
    for (int r = 0; r < 32; r++) acc[r] = 0ull;

    for (int kk = 0; kk < 64; kk++) {
        u64 w = __ldg(&wp[kk]);
#pragma unroll
        for (int r = 0; r < 32; r++) acc[r] = fma2(w, xs[r * 64 + kk], acc[r]);
    }
    const float bias = bih0[g];
    const int row0 = blockIdx.x * 32;
#pragma unroll
    for (int r = 0; r < 32; r++)
        g_xp0[(size_t)(row0 + r) * G3 + g] = hadd2(acc[r]) + bias;
}

// ============================================================================
// K2: software-pipelined 2-layer GRU. 32 blocks x 384 threads.
//   warps 0-3  (t<128) : layer 0  (j = t>>1, sub = t&1 -> half of K)
//   warps 4-11 (t>=128): layer 1  (j = (t-128)>>2, sub = &3 -> quarter K)
// Fast activations (ex2/rcp approx), distance-2 x prefetch, 1 barrier/step.
// ============================================================================
__global__ __launch_bounds__(384, 1) void k_gru(const float* __restrict__ Whh0,
                                                const float* __restrict__ Wih1,
                                                const float* __restrict__ Whh1,
                                                const float* __restrict__ bhh0,
                                                const float* __restrict__ bih1,
                                                const float* __restrict__ bhh1) {
    __shared__ float h0buf[2 * 64];
    __shared__ float h1buf[2 * 64];

    const int t = threadIdx.x;
    const int b = blockIdx.x;
    const float* xp = g_xp0 + (size_t)b * SEQ * G3;
    float* outp = g_bufA + (size_t)b * SEQ * HID;

    u64 w[48];
    float b3[3];
    float b4 = 0.0f;
    float hreg = 0.0f;
    float xa0 = 0, xa1 = 0, xa2 = 0;   // step s
    float xb0 = 0, xb1 = 0, xb2 = 0;   // step s+1
    int j, sub;

    if (t < 128) {
        j = t >> 1; sub = t & 1;
        const u64* W0 = (const u64*)Whh0;
#pragma unroll
        for (int g = 0; g < 3; g++) {
#pragma unroll
            for (int k = 0; k < 16; k++)
                w[g * 16 + k] = __ldg(&W0[(size_t)(j + 64 * g) * 32 + sub * 16 + k]);
            b3[g] = bhh0[j + 64 * g];
        }
        xa0 = xp[j]; xa1 = xp[64 + j]; xa2 = xp[128 + j];
        const float* x1r = xp + G3;
        xb0 = x1r[j]; xb1 = x1r[64 + j]; xb2 = x1r[128 + j];
        if (t < 64) { h0buf[64 + t] = 0.0f; h1buf[t] = 0.0f; }
    } else {
        const int tt = t - 128;
        j = tt >> 2; sub = tt & 3;
        const u64* Wi = (const u64*)Wih1;
        const u64* Wh = (const u64*)Whh1;
#pragma unroll
        for (int g = 0; g < 3; g++) {
#pragma unroll
            for (int k = 0; k < 8; k++) {
                w[g * 16 + k]     = __ldg(&Wi[(size_t)(j + 64 * g) * 32 + sub * 8 + k]);
                w[g * 16 + 8 + k] = __ldg(&Wh[(size_t)(j + 64 * g) * 32 + sub * 8 + k]);
            }
        }
        b3[0] = bih1[j] + bhh1[j];
        b3[1] = bih1[j + 64] + bhh1[j + 64];
        b3[2] = bih1[j + 128];
        b4    = bhh1[j + 128];
    }
    __syncthreads();

    for (int s = 0; s <= SEQ; s++) {
        if (t < 128) {
            if (s < SEQ) {
                float xn0 = 0, xn1 = 0, xn2 = 0;
                if (s + 2 < SEQ) {   // distance-2 prefetch
                    const float* xr = xp + (size_t)(s + 2) * G3;
                    xn0 = xr[j]; xn1 = xr[64 + j]; xn2 = xr[128 + j];
                }
                const u64* hb = (const u64*)(h0buf + ((s & 1) ^ 1) * 64) + sub * 16;
                u64 a0 = 0, a1 = 0, a2 = 0;
#pragma unroll
                for (int k = 0; k < 16; k++) {
                    u64 hv = hb[k];
                    a0 = fma2(w[k], hv, a0);
                    a1 = fma2(w[16 + k], hv, a1);
                    a2 = fma2(w[32 + k], hv, a2);
                }
                float d0 = hadd2(a0), d1 = hadd2(a1), d2 = hadd2(a2);
                d0 += __shfl_xor_sync(0xffffffffu, d0, 1);
                d1 += __shfl_xor_sync(0xffffffffu, d1, 1);
                d2 += __shfl_xor_sync(0xffffffffu, d2, 1);
                float rg = sigf(xa0 + d0 + b3[0]);
                float zg = sigf(xa1 + d1 + b3[1]);
                float ng = tanh_fast(xa2 + rg * (d2 + b3[2]));
                hreg = (1.0f - zg) * ng + zg * hreg;
                if (sub == 0) h0buf[(s & 1) * 64 + j] = hreg;
                xa0 = xb0; xa1 = xb1; xa2 = xb2;
                xb0 = xn0; xb1 = xn1; xb2 = xn2;
            }
        } else {
            if (s >= 1) {
                const int sl = (s & 1) ^ 1;
                const u64* hb0 = (const u64*)(h0buf + sl * 64) + sub * 8;
                const u64* hb1 = (const u64*)(h1buf + sl * 64) + sub * 8;
                u64 a0 = 0, a1 = 0, a2i = 0, a2h = 0;
#pragma unroll
                for (int k = 0; k < 8; k++) {
                    u64 h0v = hb0[k], h1v = hb1[k];
                    a0  = fma2(w[k],      h0v, a0);
                    a0  = fma2(w[8 + k],  h1v, a0);
                    a1  = fma2(w[16 + k], h0v, a1);
                    a1  = fma2(w[24 + k], h1v, a1);
                    a2i = fma2(w[32 + k], h0v, a2i);
                    a2h = fma2(w[40 + k], h1v, a2h);
                }
                float d0 = hadd2(a0), d1 = hadd2(a1);
                float di = hadd2(a2i), dh = hadd2(a2h);
                d0 += __shfl_xor_sync(0xffffffffu, d0, 1);
                d1 += __shfl_xor_sync(0xffffffffu, d1, 1);
                di += __shfl_xor_sync(0xffffffffu, di, 1);
                dh += __shfl_xor_sync(0xffffffffu, dh, 1);
                d0 += __shfl_xor_sync(0xffffffffu, d0, 2);
                d1 += __shfl_xor_sync(0xffffffffu, d1, 2);
                di += __shfl_xor_sync(0xffffffffu, di, 2);
                dh += __shfl_xor_sync(0xffffffffu, dh, 2);
                float rg = sigf(d0 + b3[0]);
                float zg = sigf(d1 + b3[1]);
                float ng = tanh_fast(di + b3[2] + rg * (dh + b4));
                hreg = (1.0f - zg) * ng + zg * hreg;
                if (sub == 0) {
                    h1buf[(s & 1) * 64 + j] = hreg;
                    outp[(size_t)(s - 1) * HID + j] = hreg;
                }
            }
        }
        __syncthreads();
    }
}

// ============================================================================
// K3: fused SINDy layer. 125 blocks x 256 threads.
// Phase A: split-K register-tiled smem GEMM. Two 128-thread halves each do
// half of every 64-K chunk with an 8-row x 8-col thread tile (4 LDS.128 per
// 32 fma2); packed-f32x2 cross-half reduction at the end. Theta chunks built
// on the fly (mul.f32x2) from transposed z; double-buffered Theta/coef.
// ----------------------------------------------------------------------------
// dyn smem (bytes):
//  A: zT  @0       [65][132] f   34,320   (row 64 == 1.0 column)
//     th0 @34,320  [64][132] f   33,792   (also reduction buffer at the end)
//     th1 @68,112  [64][132] f   33,792
//     cc0 @101,904 [64][64]  f   16,384
//     cc1 @118,288 [64][64]  f   16,384
//     ta  @134,672 u8 x 2 x 2145  4,352
//  C: s1f @0       [128][66] f   33,792
//     w1s @33,792  [128][66] f   33,792
//     w2t @67,584  [128][66] f   33,792
//     h1s @101,376 [128][129] f  66,048
//  par   @167,424  448 f          1,792
#define SINDY_SMEM 169216

__global__ __launch_bounds__(256, 1) void k_sindy(int layer, float* __restrict__ out_ext,
                                                  const float* __restrict__ coef,
                                                  const float* __restrict__ g1,
                                                  const float* __restrict__ b1n,
                                                  const float* __restrict__ W1,
                                                  const float* __restrict__ bf1,
                                                  const float* __restrict__ W2,
                                                  const float* __restrict__ bf2,
                                                  const float* __restrict__ g2,
                                                  const float* __restrict__ b2n) {
    extern __shared__ char sm[];
    float* zT  = (float*)sm;                        // [65][132]
    float* th0 = (float*)(sm + 34320);
    float* th1 = (float*)(sm + 68112);
    float* cc0 = (float*)(sm + 101904);
    float* cc1 = (float*)(sm + 118288);
    unsigned char* ta = (unsigned char*)(sm + 134672);
    float* s1f = (float*)sm;                        // [128][66] (phase C)
    float* w1s = (float*)(sm + 33792);
    float* w2t = (float*)(sm + 67584);
    float* h1s = (float*)(sm + 101376);             // [128][129]
    float* par = (float*)(sm + 167424);
    u64*   red = (u64*)th0;                         // [128][33] reduction buffer

    const float* in = (layer == 0) ? g_bufA : g_bufB;
    float* outp     = (layer == 0) ? g_bufB : out_ext;
    float* tail     = out_ext + NROW * HID;
    const int final_layer = (layer == 1);

    const int t = threadIdx.x;
    const int row0 = blockIdx.x * 128;

    // ---- load z transposed (+ ones row 64), params, index table ----
    const float* inb = in + (size_t)row0 * HID;
    for (int idx = t; idx < 128 * 64; idx += 256) {
        int r = idx >> 6, c = idx & 63;
        zT[c * 132 + r] = inb[idx];
    }
    if (t < 128) zT[64 * 132 + t] = 1.0f;

    for (int idx = t; idx < 448; idx += 256) {
        float v;
        if      (idx < 64)  v = g1[idx];
        else if (idx < 128) v = b1n[idx - 64];
        else if (idx < 192) v = g2[idx - 128];
        else if (idx < 256) v = b2n[idx - 192];
        else if (idx < 384) v = bf1[idx - 256];
        else                v = bf2[idx - 384];
        par[idx] = v;
    }

    for (int k = t; k < NLIB; k += 256) {
        int i, j;
        if (k == 0)      { i = 64; j = 64; }
        else if (k < 65) { i = k - 1; j = 64; }
        else {
            int q = k - 65;
            i = (int)floorf((129.0f - sqrtf(16641.0f - 8.0f * (float)q)) * 0.5f);
            if (i < 0) i = 0; if (i > 63) i = 63;
            while (i < 63 && ((i + 1) * 64 - (i + 1) * i / 2) <= q) i++;
            while (i > 0 && (i * 64 - i * (i - 1) / 2) > q) i--;
            j = i + (q - (i * 64 - i * (i - 1) / 2));
        }
        ta[2 * k]     = (unsigned char)i;
        ta[2 * k + 1] = (unsigned char)j;
    }
    __syncthreads();

    // ---- phase A: upd = Theta @ coef, split-K 8x8 register tiles ----
    const int half = t >> 7;              // 0/1: which K half of each chunk
    const int tt   = t & 127;
    const int tx   = tt & 7;              // col group: c0 = tx*8
    const int ty   = tt >> 3;             // row group: r0 = ty*8
    const int c0 = tx * 8, r0 = ty * 8;

    u64 acc[32];    // acc[rp*8+jc]: rows (r0+2rp, r0+2rp+1), col c0+jc
#pragma unroll
    for (int u = 0; u < 32; u++) acc[u] = 0ull;

    // prologue: stage chunk 0 (all 256 threads)
    {
        const float4* src4 = (const float4*)coef;
        float4* dst4 = (float4*)cc0;
#pragma unroll
        for (int ii = 0; ii < 4; ii++) dst4[t + ii * 256] = src4[t + ii * 256];
#pragma unroll
        for (int ii = 0; ii < 8; ii++) {
            int idx = t + ii * 256;
            int kk = idx >> 5, rq = idx & 31;
            int i = ta[2 * kk], j = ta[2 * kk + 1];
            ulonglong2 zi = *(const ulonglong2*)(zT + i * 132 + rq * 4);
            ulonglong2 zj = *(const ulonglong2*)(zT + j * 132 + rq * 4);
            ulonglong2 o; o.x = mul2(zi.x, zj.x); o.y = mul2(zi.y, zj.y);
            *(ulonglong2*)(th0 + kk * 132 + rq * 4) = o;
        }
    }
    __syncthreads();

    for (int cn = 0; cn < NCH; cn++) {
        const float* thc = (cn & 1) ? th1 : th0;
        const float* ccc = (cn & 1) ? cc1 : cc0;
        float* thn = (cn & 1) ? th0 : th1;
        float* ccn = (cn & 1) ? cc0 : cc1;
        const int kb_n = (cn + 1) * 64;
        const int klen_n = (kb_n < NLIB) ? ((NLIB - kb_n < 64) ? (NLIB - kb_n) : 64) : 0;
        const int klen   = (NLIB - cn * 64 < 64) ? (NLIB - cn * 64) : 64;

        // prefetch next coef chunk into registers
        float4 cr[4];
        if (klen_n > 0) {
            const float4* src4 = (const float4*)(coef + (size_t)kb_n * 64);
            const int lim = klen_n * 16;
#pragma unroll
            for (int ii = 0; ii < 4; ii++) {
                int idx = t + ii * 256;
                if (idx < lim) cr[ii] = src4[idx];
            }
        }

        // this half's K range within the chunk
        int ks = half * 32;
        int ke = ks + 32;
        if (ke > klen) ke = klen;
        if (ks > klen) ks = klen;

#pragma unroll 2
        for (int kk = ks; kk < ke; kk++) {
            ulonglong2 q0 = *(const ulonglong2*)(thc + kk * 132 + r0);      // rows r0..r0+3
            ulonglong2 q1 = *(const ulonglong2*)(thc + kk * 132 + r0 + 4);  // rows r0+4..r0+7
            float4 ca = *(const float4*)(ccc + kk * 64 + c0);
            float4 cb = *(const float4*)(ccc + kk * 64 + c0 + 4);
            u64 b0 = bcast2(ca.x), b1 = bcast2(ca.y), b2 = bcast2(ca.z), b3 = bcast2(ca.w);
            u64 b4 = bcast2(cb.x), b5 = bcast2(cb.y), b6 = bcast2(cb.z), b7 = bcast2(cb.w);
            acc[0]  = fma2(q0.x, b0, acc[0]);  acc[1]  = fma2(q0.x, b1, acc[1]);
            acc[2]  = fma2(q0.x, b2, acc[2]);  acc[3]  = fma2(q0.x, b3, acc[3]);
            acc[4]  = fma2(q0.x, b4, acc[4]);  acc[5]  = fma2(q0.x, b5, acc[5]);
            acc[6]  = fma2(q0.x, b6, acc[6]);  acc[7]  = fma2(q0.x, b7, acc[7]);
            acc[8]  = fma2(q0.y, b0, acc[8]);  acc[9]  = fma2(q0.y, b1, acc[9]);
            acc[10] = fma2(q0.y, b2, acc[10]); acc[11] = fma2(q0.y, b3, acc[11]);
            acc[12] = fma2(q0.y, b4, acc[12]); acc[13] = fma2(q0.y, b5, acc[13]);
            acc[14] = fma2(q0.y, b6, acc[14]); acc[15] = fma2(q0.y, b7, acc[15]);
            acc[16] = fma2(q1.x, b0, acc[16]); acc[17] = fma2(q1.x, b1, acc[17]);
            acc[18] = fma2(q1.x, b2, acc[18]); acc[19] = fma2(q1.x, b3, acc[19]);
            acc[20] = fma2(q1.x, b4, acc[20]); acc[21] = fma2(q1.x, b5, acc[21]);
            acc[22] = fma2(q1.x, b6, acc[22]); acc[23] = fma2(q1.x, b7, acc[23]);
            acc[24] = fma2(q1.y, b0, acc[24]); acc[25] = fma2(q1.y, b1, acc[25]);
            acc[26] = fma2(q1.y, b2, acc[26]); acc[27] = fma2(q1.y, b3, acc[27]);
            acc[28] = fma2(q1.y, b4, acc[28]); acc[29] = fma2(q1.y, b5, acc[29]);
            acc[30] = fma2(q1.y, b6, acc[30]); acc[31] = fma2(q1.y, b7, acc[31]);
        }

        // stage next chunk (coef STS + theta build), all 256 threads
        if (klen_n > 0) {
            float4* dst4 = (float4*)ccn;
            const int lim = klen_n * 16;
#pragma unroll
            for (int ii = 0; ii < 4; ii++) {
                int idx = t + ii * 256;
                if (idx < lim) dst4[idx] = cr[ii];
            }
#pragma unroll
            for (int ii = 0; ii < 8; ii++) {
                int idx = t + ii * 256;
                int kk = idx >> 5, rq = idx & 31;
                if (kk < klen_n) {
                    int i = ta[2 * (kb_n + kk)], j = ta[2 * (kb_n + kk) + 1];
                    ulonglong2 zi = *(const ulonglong2*)(zT + i * 132 + rq * 4);
                    ulonglong2 zj = *(const ulonglong2*)(zT + j * 132 + rq * 4);
                    ulonglong2 o; o.x = mul2(zi.x, zj.x); o.y = mul2(zi.y, zj.y);
                    *(ulonglong2*)(thn + kk * 132 + rq * 4) = o;
                }
            }
        }
        __syncthreads();
    }

    // ---- cross-half reduction (packed adds) ----
    if (half == 1) {
#pragma unroll
        for (int u = 0; u < 32; u++) red[tt * 33 + u] = acc[u];
    }
    __syncthreads();
    if (half == 0) {
#pragma unroll
        for (int u = 0; u < 32; u++) acc[u] = add2(acc[u], red[tt * 33 + u]);
        // residual: rows (r0+2rp, r0+2rp+1) are contiguous in zT column c0+jc
#pragma unroll
        for (int rp = 0; rp < 4; rp++)
#pragma unroll
            for (int jc = 0; jc < 8; jc++)
                acc[rp * 8 + jc] = add2(acc[rp * 8 + jc],
                    *(const u64*)(zT + (c0 + jc) * 132 + r0 + 2 * rp));
    }
    __syncthreads();   // zT reads done; s1f may now overwrite it
    if (half == 0) {
#pragma unroll
        for (int rp = 0; rp < 4; rp++)
#pragma unroll
            for (int jc = 0; jc < 8; jc++) {
                float v0, v1; unpack2(acc[rp * 8 + jc], v0, v1);
                s1f[(r0 + 2 * rp) * 66 + c0 + jc]     = v0;
                s1f[(r0 + 2 * rp + 1) * 66 + c0 + jc] = v1;
            }
    }
    __syncthreads();

    // LN1 (half the threads) runs while the others stage W1 / W2^T
    if (t < 128) {
        float* rowp = s1f + t * 66;
        float s = 0.0f, s2 = 0.0f;
        for (int c = 0; c < 64; c++) { float v = rowp[c]; s += v; s2 += v * v; }
        float m = s * (1.0f / 64.0f);
        float inv = rsqrtf(s2 * (1.0f / 64.0f) - m * m + 1e-5f);
        for (int c = 0; c < 64; c++)
            rowp[c] = (rowp[c] - m) * inv * par[c] + par[64 + c];
    } else {
        const int t2 = t - 128;
        for (int idx = t2; idx < 128 * 64; idx += 128) {
            int f = idx >> 6, c = idx & 63;
            w1s[f * 66 + c] = W1[idx];
        }
        for (int idx = t2; idx < 64 * 128; idx += 128) {
            int c = idx >> 7, f = idx & 127;
            w2t[f * 66 + c] = W2[idx];
        }
    }
    __syncthreads();

    // ---- phase C1: FF1 -> gelu -> h1s ----
    const int r = t >> 1;
    const int p = t & 1;
    {
        u64 s1r[32];
        const u64* srow = (const u64*)(s1f + r * 66);
#pragma unroll
        for (int cc = 0; cc < 32; cc++) s1r[cc] = srow[cc];
        for (int f0 = 0; f0 < 64; f0++) {
            int f = p * 64 + f0;
            u64 a = 0ull;
            const u64* wrow = (const u64*)(w1s + f * 66);
#pragma unroll
            for (int cc = 0; cc < 32; cc++) a = fma2(s1r[cc], wrow[cc], a);
            float v = hadd2(a) + par[256 + f];
            h1s[r * 129 + f] = 0.5f * v * (1.0f + erff(v * 0.70710678118654752f));
        }
    }
    __syncthreads();

    // ---- phase C2: FF2 + residual + LN2 (register LN via shfl partner) ----
    {
        u64 acc3[16];
#pragma unroll
        for (int u = 0; u < 16; u++) {
            int c = p * 32 + 2 * u;
            acc3[u] = pack2(s1f[r * 66 + c] + par[384 + c],
                            s1f[r * 66 + c + 1] + par[384 + c + 1]);
        }
        const float* hrow = h1s + r * 129;
        for (int f = 0; f < 128; f++) {
            u64 a2 = bcast2(hrow[f]);
            const u64* wrow = (const u64*)(w2t + f * 66) + p * 16;
#pragma unroll
            for (int u = 0; u < 16; u++) acc3[u] = fma2(a2, wrow[u], acc3[u]);
        }
        float ov[32];
        float s = 0.0f, s2 = 0.0f;
#pragma unroll
        for (int u = 0; u < 16; u++) {
            float x0, x1; unpack2(acc3[u], x0, x1);
            ov[2 * u] = x0; ov[2 * u + 1] = x1;
            s += x0 + x1; s2 += x0 * x0 + x1 * x1;
        }
        s  += __shfl_xor_sync(0xffffffffu, s, 1);
        s2 += __shfl_xor_sync(0xffffffffu, s2, 1);
        float m = s * (1.0f / 64.0f);
        float inv = rsqrtf(s2 * (1.0f / 64.0f) - m * m + 1e-5f);
#pragma unroll
        for (int u = 0; u < 32; u++)
            ov[u] = (ov[u] - m) * inv * par[128 + p * 32 + u] + par[192 + p * 32 + u];

        const int grow = row0 + r;
        float2* op2 = (float2*)(outp + (size_t)grow * HID + p * 32);
#pragma unroll
        for (int u = 0; u < 16; u++) op2[u] = make_float2(ov[2 * u], ov[2 * u + 1]);

        if (final_layer && (grow % SEQ) == (SEQ - 1)) {
            float* tp = tail + (grow / SEQ) * HID + p * 32;
#pragma unroll
            for (int u = 0; u < 32; u++) tp[u] = ov[u];
        }
    }
}

// ============================================================================
extern "C" void kernel_launch(void* const* d_in, const int* in_sizes, int n_in,
                              void* d_out, int out_size) {
    const float* x     = (const float*)d_in[0];
    const float* Wih0  = (const float*)d_in[1];
    const float* Whh0  = (const float*)d_in[2];
    const float* bih0  = (const float*)d_in[3];
    const float* bhh0  = (const float*)d_in[4];
    const float* Wih1  = (const float*)d_in[5];
    const float* Whh1  = (const float*)d_in[6];
    const float* bih1  = (const float*)d_in[7];
    const float* bhh1  = (const float*)d_in[8];
    const float* coeffs= (const float*)d_in[9];
    const float* ln1_g = (const float*)d_in[10];
    const float* ln1_b = (const float*)d_in[11];
    const float* W1    = (const float*)d_in[12];
    const float* b1    = (const float*)d_in[13];
    const float* W2    = (const float*)d_in[14];
    const float* b2    = (const float*)d_in[15];
    const float* ln2_g = (const float*)d_in[16];
    const float* ln2_b = (const float*)d_in[17];
    float* out = (float*)d_out;

    cudaFuncSetAttribute(k_sindy, cudaFuncAttributeMaxDynamicSharedMemorySize, SINDY_SMEM);

    k_xp0<<<500, 192>>>(x, Wih0, bih0);
    k_gru<<<32, 384>>>(Whh0, Wih1, Whh1, bhh0, bih1, bhh1);

    for (int l = 0; l < 2; l++) {
        k_sindy<<<125, 256, SINDY_SMEM>>>(l, out,
            coeffs + (size_t)l * NLIB * HID,
            ln1_g + l * HID, ln1_b + l * HID,
            W1 + (size_t)l * FFD * HID, b1 + l * FFD,
            W2 + (size_t)l * HID * FFD, b2 + l * HID,
            ln2_g + l * HID, ln2_b + l * HID);
    }
}

// round 12
// speedup vs baseline: 3.1882x; 1.0567x over previous
#include <cuda_runtime.h>

typedef unsigned long long u64;

#define BATCH 32
#define SEQ   500
#define DM    128
#define HID   64
#define G3    192        // 3*HID
#define NROW  16000      // BATCH*SEQ
#define NLIB  2145
#define FFD   128

// ---------------- scratch (device globals; no allocation allowed) ----------
__device__ float g_xp0[BATCH * SEQ * G3];    // input projections for GRU L0
__device__ float g_bufA[NROW * HID];         // GRU output
__device__ float g_bufB[NROW * HID];         // SINDy layer 0 output

// ---------------- packed f32x2 helpers ------------------------------------
__device__ __forceinline__ u64 fma2(u64 a, u64 b, u64 c) {
    u64 d; asm("fma.rn.f32x2 %0, %1, %2, %3;" : "=l"(d) : "l"(a), "l"(b), "l"(c)); return d;
}
__device__ __forceinline__ u64 pack2(float x, float y) {
    u64 r; asm("mov.b64 %0, {%1, %2};" : "=l"(r) : "f"(x), "f"(y)); return r;
}
__device__ __forceinline__ u64 bcast2(float x) {
    u64 r; asm("mov.b64 %0, {%1, %1};" : "=l"(r) : "f"(x)); return r;
}
__device__ __forceinline__ void unpack2(u64 v, float& x, float& y) {
    asm("mov.b64 {%0, %1}, %2;" : "=f"(x), "=f"(y) : "l"(v));
}
__device__ __forceinline__ float hadd2(u64 v) { float x, y; unpack2(v, x, y); return x + y; }

// fast activations: ex2.approx + rcp.approx -> ~1e-6 rel err
__device__ __forceinline__ float fast_rcp(float x) {
    float r; asm("rcp.approx.f32 %0, %1;" : "=f"(r) : "f"(x)); return r;
}
__device__ __forceinline__ float fast_ex2(float x) {
    float r; asm("ex2.approx.f32 %0, %1;" : "=f"(r) : "f"(x)); return r;
}
__device__ __forceinline__ float sigf(float v) {
    return fast_rcp(1.0f + fast_ex2(-1.4426950408889634f * v));
}
__device__ __forceinline__ float tanh_fast(float v) {
    float e = fast_ex2(2.8853900817779268f * v);
    return 1.0f - 2.0f * fast_rcp(e + 1.0f);
}

// named barriers
__device__ __forceinline__ void bar_sync(int id, int cnt) {
    asm volatile("bar.sync %0, %1;" :: "r"(id), "r"(cnt) : "memory");
}
__device__ __forceinline__ void bar_arrive(int id, int cnt) {
    asm volatile("bar.arrive %0, %1;" :: "r"(id), "r"(cnt) : "memory");
}

// ============================================================================
// K1: g_xp0[row][g] = bih0[g] + sum_k x[row][k] * Wih0[g][k]
// ============================================================================
__global__ __launch_bounds__(192) void k_xp0(const float* __restrict__ x,
                                             const float* __restrict__ Wih0,
                                             const float* __restrict__ bih0) {
    __shared__ u64 xs[32 * 64];
    const int g = threadIdx.x;
    const u64* x2 = (const u64*)x + (size_t)blockIdx.x * 2048;
    for (int idx = g; idx < 2048; idx += 192) xs[idx] = x2[idx];
    __syncthreads();

    const u64* wp = (const u64*)Wih0 + (size_t)g * 64;
    u64 acc[32];
#pragma unroll
    for (int r = 0; r < 32; r++) acc[r] = 0ull;

    for (int kk = 0; kk < 64; kk++) {
        u64 w = __ldg(&wp[kk]);
#pragma unroll
        for (int r = 0; r < 32; r++) acc[r] = fma2(w, xs[r * 64 + kk], acc[r]);
    }
    const float bias = bih0[g];
    const int row0 = blockIdx.x * 32;
#pragma unroll
    for (int r = 0; r < 32; r++)
        g_xp0[(size_t)(row0 + r) * G3 + g] = hadd2(acc[r]) + bias;
}

// ============================================================================
// K2: decoupled 2-layer GRU. 32 blocks x 384 threads.
//   warps 0-3  (t<128) : layer 0, h0 -> depth-4 smem ring
//   warps 4-11 (t>=128): layer 1, consumes ring
// Cross-group sync via named-barrier producer/consumer (A=full, B=free):
//   L0 step s:  [s>=4: sync B]  compute h0[s] from ring[(s-1)%4], STS ring[s%4],
//               sync D(128, in-group), arrive A
//   L1 step u:  sync A (h0[u] ready), compute h1[u], arrive B, STS h1/out,
//               sync C(256, in-group)
// Arrival accounting: A: 128 arr + 256 sync, 500 phases each side.
//                     B: 256 arr x500, 128 sync x496 (last 4 phases unwaited).
// ============================================================================
__global__ __launch_bounds__(384, 1) void k_gru(const float* __restrict__ Whh0,
                                                const float* __restrict__ Wih1,
                                                const float* __restrict__ Whh1,
                                                const float* __restrict__ bhh0,
                                                const float* __restrict__ bih1,
                                                const float* __restrict__ bhh1) {
    __shared__ float ring[4 * 64];    // h0 ring, 4 slots
    __shared__ float h1buf[2 * 64];

    const int t = threadIdx.x;
    const int b = blockIdx.x;
    const float* xp = g_xp0 + (size_t)b * SEQ * G3;
    float* outp = g_bufA + (size_t)b * SEQ * HID;

    u64 w[48];
    float b3[3];
    float b4 = 0.0f;
    float hreg = 0.0f;
    int j, sub;

    if (t < 128) {
        j = t >> 1; sub = t & 1;
        const u64* W0 = (const u64*)Whh0;
#pragma unroll
        for (int g = 0; g < 3; g++) {
#pragma unroll
            for (int k = 0; k < 16; k++)
                w[g * 16 + k] = __ldg(&W0[(size_t)(j + 64 * g) * 32 + sub * 16 + k]);
            b3[g] = bhh0[j + 64 * g];
        }
    } else {
        const int tt = t - 128;
        j = tt >> 2; sub = tt & 3;
        const u64* Wi = (const u64*)Wih1;
        const u64* Wh = (const u64*)Whh1;
#pragma unroll
        for (int g = 0; g < 3; g++) {
#pragma unroll
            for (int k = 0; k < 8; k++) {
                w[g * 16 + k]     = __ldg(&Wi[(size_t)(j + 64 * g) * 32 + sub * 8 + k]);
                w[g * 16 + 8 + k] = __ldg(&Wh[(size_t)(j + 64 * g) * 32 + sub * 8 + k]);
            }
        }
        b3[0] = bih1[j] + bhh1[j];
        b3[1] = bih1[j + 64] + bhh1[j + 64];
        b3[2] = bih1[j + 128];
        b4    = bhh1[j + 128];
    }
    // zero shared state
    if (t < 128) { ring[t] = 0.0f; ring[128 + t] = 0.0f; }
    else if (t < 256) { h1buf[t - 128] = 0.0f; }
    __syncthreads();

    if (t < 128) {
        // ---------------- layer 0 producer ----------------
        float xa0 = xp[j], xa1 = xp[64 + j], xa2 = xp[128 + j];
        const float* x1r = xp + G3;
        float xb0 = x1r[j], xb1 = x1r[64 + j], xb2 = x1r[128 + j];

        for (int s = 0; s < SEQ; s++) {
            float xn0 = 0, xn1 = 0, xn2 = 0;
            if (s + 2 < SEQ) {
                const float* xr = xp + (size_t)(s + 2) * G3;
                xn0 = xr[j]; xn1 = xr[64 + j]; xn2 = xr[128 + j];
            }
            const u64* hb = (const u64*)(ring + ((s + 3) & 3) * 64) + sub * 16;
            u64 a0 = 0, a1 = 0, a2 = 0;
#pragma unroll
            for (int k = 0; k < 16; k++) {
                u64 hv = hb[k];
                a0 = fma2(w[k], hv, a0);
                a1 = fma2(w[16 + k], hv, a1);
                a2 = fma2(w[32 + k], hv, a2);
            }
            float d0 = hadd2(a0), d1 = hadd2(a1), d2 = hadd2(a2);
            d0 += __shfl_xor_sync(0xffffffffu, d0, 1);
            d1 += __shfl_xor_sync(0xffffffffu, d1, 1);
            d2 += __shfl_xor_sync(0xffffffffu, d2, 1);
            float rg = sigf(xa0 + d0 + b3[0]);
            float zg = sigf(xa1 + d1 + b3[1]);
            float ng = tanh_fast(xa2 + rg * (d2 + b3[2]));
            hreg = (1.0f - zg) * ng + zg * hreg;

            if (s >= 4) bar_sync(5, 384);          // slot s%4 free (L1 done with s-4)
            if (sub == 0) ring[(s & 3) * 64 + j] = hreg;
            bar_sync(3, 128);                       // in-group: h0[s] complete (drains STS)
            bar_arrive(1, 384);                     // publish h0[s]

            xa0 = xb0; xa1 = xb1; xa2 = xb2;
            xb0 = xn0; xb1 = xn1; xb2 = xn2;
        }
    } else {
        // ---------------- layer 1 consumer ----------------
        for (int u = 0; u < SEQ; u++) {
            bar_sync(1, 384);                       // h0[u] ready
            const u64* hb0 = (const u64*)(ring + (u & 3) * 64) + sub * 8;
            const u64* hb1 = (const u64*)(h1buf + ((u & 1) ^ 1) * 64) + sub * 8;
            u64 a0 = 0, a1 = 0, a2i = 0, a2h = 0;
#pragma unroll
            for (int k = 0; k < 8; k++) {
                u64 h0v = hb0[k], h1v = hb1[k];
                a0  = fma2(w[k],      h0v, a0);
                a0  = fma2(w[8 + k],  h1v, a0);
                a1  = fma2(w[16 + k], h0v, a1);
                a1  = fma2(w[24 + k], h1v, a1);
                a2i = fma2(w[32 + k], h0v, a2i);
                a2h = fma2(w[40 + k], h1v, a2h);
            }
            float d0 = hadd2(a0), d1 = hadd2(a1);
            float di = hadd2(a2i), dh = hadd2(a2h);
            d0 += __shfl_xor_sync(0xffffffffu, d0, 1);
            d1 += __shfl_xor_sync(0xffffffffu, d1, 1);
            di += __shfl_xor_sync(0xffffffffu, di, 1);
            dh += __shfl_xor_sync(0xffffffffu, dh, 1);
            d0 += __shfl_xor_sync(0xffffffffu, d0, 2);
            d1 += __shfl_xor_sync(0xffffffffu, d1, 2);
            di += __shfl_xor_sync(0xffffffffu, di, 2);
            dh += __shfl_xor_sync(0xffffffffu, dh, 2);
            float rg = sigf(d0 + b3[0]);
            float zg = sigf(d1 + b3[1]);
            float ng = tanh_fast(di + b3[2] + rg * (dh + b4));
            hreg = (1.0f - zg) * ng + zg * hreg;

            bar_arrive(5, 384);                     // done reading ring slot u%4
            if (sub == 0) {
                h1buf[(u & 1) * 64 + j] = hreg;
                outp[(size_t)u * HID + j] = hreg;
            }
            bar_sync(2, 256);                       // in-group recurrence barrier
        }
    }
}

// ============================================================================
// K3: fused SINDy layer (R6 version — best measured: 172.6 us/layer).
// 125 blocks x 256 threads; register-tiled smem GEMM (8 rows x 4 cols),
// on-the-fly Theta chunks, double-buffered Theta/coef.
// ============================================================================
#define SINDY_SMEM 169216

__global__ __launch_bounds__(256, 1) void k_sindy(int layer, float* __restrict__ out_ext,
                                                  const float* __restrict__ coef,
                                                  const float* __restrict__ g1,
                                                  const float* __restrict__ b1n,
                                                  const float* __restrict__ W1,
                                                  const float* __restrict__ bf1,
                                                  const float* __restrict__ W2,
                                                  const float* __restrict__ bf2,
                                                  const float* __restrict__ g2,
                                                  const float* __restrict__ b2n) {
    extern __shared__ char sm[];
    float* zT  = (float*)sm;                        // [65][132]
    float* th0 = (float*)(sm + 34320);
    float* th1 = (float*)(sm + 68112);
    float* cc0 = (float*)(sm + 101904);
    float* cc1 = (float*)(sm + 118288);
    unsigned char* ta = (unsigned char*)(sm + 134672);
    float* s1f = (float*)sm;                        // [128][66] (phase C)
    float* w1s = (float*)(sm + 33792);
    float* w2t = (float*)(sm + 67584);
    float* h1s = (float*)(sm + 101376);             // [128][129]
    float* par = (float*)(sm + 167424);

    const float* in = (layer == 0) ? g_bufA : g_bufB;
    float* outp     = (layer == 0) ? g_bufB : out_ext;
    float* tail     = out_ext + NROW * HID;
    const int final_layer = (layer == 1);

    const int t = threadIdx.x;
    const int row0 = blockIdx.x * 128;

    // ---- load z transposed (+ ones row 64), params, index table ----
    const float* inb = in + (size_t)row0 * HID;
    for (int idx = t; idx < 128 * 64; idx += 256) {
        int r = idx >> 6, c = idx & 63;
        zT[c * 132 + r] = inb[idx];
    }
    if (t < 128) zT[64 * 132 + t] = 1.0f;

    for (int idx = t; idx < 448; idx += 256) {
        float v;
        if      (idx < 64)  v = g1[idx];
        else if (idx < 128) v = b1n[idx - 64];
        else if (idx < 192) v = g2[idx - 128];
        else if (idx < 256) v = b2n[idx - 192];
        else if (idx < 384) v = bf1[idx - 256];
        else                v = bf2[idx - 384];
        par[idx] = v;
    }

    for (int k = t; k < NLIB; k += 256) {
        int i, j;
        if (k == 0)      { i = 64; j = 64; }
        else if (k < 65) { i = k - 1; j = 64; }
        else {
            int q = k - 65;
            i = (int)floorf((129.0f - sqrtf(16641.0f - 8.0f * (float)q)) * 0.5f);
            if (i < 0) i = 0; if (i > 63) i = 63;
            while (i < 63 && ((i + 1) * 64 - (i + 1) * i / 2) <= q) i++;
            while (i > 0 && (i * 64 - i * (i - 1) / 2) > q) i--;
            j = i + (q - (i * 64 - i * (i - 1) / 2));
        }
        ta[2 * k]     = (unsigned char)i;
        ta[2 * k + 1] = (unsigned char)j;
    }
    __syncthreads();

    // ---- phase A: upd = Theta @ coef, register-tiled, double-buffered ----
    const int tx = t & 15, ty = t >> 4;
    const int c0 = tx * 4, r0 = ty * 8;

    u64 acc[16];    // acc[rp*4 + jc]: rows (r0+2rp, r0+2rp+1), col c0+jc
#pragma unroll
    for (int u = 0; u < 16; u++) acc[u] = 0ull;

    // prologue: stage chunk 0
    {
        const float4* src4 = (const float4*)coef;
        float4* dst4 = (float4*)cc0;
#pragma unroll
        for (int ii = 0; ii < 4; ii++) dst4[t + ii * 256] = src4[t + ii * 256];
#pragma unroll
        for (int ii = 0; ii < 8; ii++) {
            int idx = t + ii * 256;
            int kk = idx >> 5, rq = idx & 31;
            int i = ta[2 * kk], j = ta[2 * kk + 1];
            float4 zi = *(const float4*)(zT + i * 132 + rq * 4);
            float4 zj = *(const float4*)(zT + j * 132 + rq * 4);
            float4 o = make_float4(zi.x * zj.x, zi.y * zj.y, zi.z * zj.z, zi.w * zj.w);
            *(float4*)(th0 + kk * 132 + rq * 4) = o;
        }
    }
    __syncthreads();

    for (int cn = 0; cn * 64 < NLIB; cn++) {
        const float* thc = (cn & 1) ? th1 : th0;
        const float* ccc = (cn & 1) ? cc1 : cc0;
        float* thn = (cn & 1) ? th0 : th1;
        float* ccn = (cn & 1) ? cc0 : cc1;
        const int kb_n = (cn + 1) * 64;
        const int klen_n = (kb_n < NLIB) ? ((NLIB - kb_n < 64) ? (NLIB - kb_n) : 64) : 0;
        const int klen   = (NLIB - cn * 64 < 64) ? (NLIB - cn * 64) : 64;

        // prefetch next coef chunk into registers (overlaps with fma loop)
        float4 cr[4];
        if (klen_n > 0) {
            const float4* src4 = (const float4*)(coef + (size_t)kb_n * 64);
            const int lim = klen_n * 16;
#pragma unroll
            for (int ii = 0; ii < 4; ii++) {
                int idx = t + ii * 256;
                if (idx < lim) cr[ii] = src4[idx];
            }
        }

        // main fma loop over this chunk
#pragma unroll 4
        for (int kk = 0; kk < klen; kk++) {
            ulonglong2 q0 = *(const ulonglong2*)(thc + kk * 132 + r0);      // rows r0..r0+3
            ulonglong2 q1 = *(const ulonglong2*)(thc + kk * 132 + r0 + 4);  // rows r0+4..r0+7
            float4 cf = *(const float4*)(ccc + kk * 64 + c0);
            u64 b0 = bcast2(cf.x), b1 = bcast2(cf.y), b2 = bcast2(cf.z), b3 = bcast2(cf.w);
            acc[0]  = fma2(q0.x, b0, acc[0]);  acc[1]  = fma2(q0.x, b1, acc[1]);
            acc[2]  = fma2(q0.x, b2, acc[2]);  acc[3]  = fma2(q0.x, b3, acc[3]);
            acc[4]  = fma2(q0.y, b0, acc[4]);  acc[5]  = fma2(q0.y, b1, acc[5]);
            acc[6]  = fma2(q0.y, b2, acc[6]);  acc[7]  = fma2(q0.y, b3, acc[7]);
            acc[8]  = fma2(q1.x, b0, acc[8]);  acc[9]  = fma2(q1.x, b1, acc[9]);
            acc[10] = fma2(q1.x, b2, acc[10]); acc[11] = fma2(q1.x, b3, acc[11]);
            acc[12] = fma2(q1.y, b0, acc[12]); acc[13] = fma2(q1.y, b1, acc[13]);
            acc[14] = fma2(q1.y, b2, acc[14]); acc[15] = fma2(q1.y, b3, acc[15]);
        }

        // stage next chunk (coef STS + theta build) into the other buffer
        if (klen_n > 0) {
            float4* dst4 = (float4*)ccn;
            const int lim = klen_n * 16;
#pragma unroll
            for (int ii = 0; ii < 4; ii++) {
                int idx = t + ii * 256;
                if (idx < lim) dst4[idx] = cr[ii];
            }
#pragma unroll
            for (int ii = 0; ii < 8; ii++) {
                int idx = t + ii * 256;
                int kk = idx >> 5, rq = idx & 31;
                if (kk < klen_n) {
                    int i = ta[2 * (kb_n + kk)], j = ta[2 * (kb_n + kk) + 1];
                    float4 zi = *(const float4*)(zT + i * 132 + rq * 4);
                    float4 zj = *(const float4*)(zT + j * 132 + rq * 4);
                    float4 o = make_float4(zi.x * zj.x, zi.y * zj.y, zi.z * zj.z, zi.w * zj.w);
                    *(float4*)(thn + kk * 132 + rq * 4) = o;
                }
            }
        }
        __syncthreads();
    }

    // ---- phase B: residual (read zT into regs), then write s1f (aliases zT) ----
    float vals[32];   // vals[rr*4 + jc] = row r0+rr, col c0+jc
#pragma unroll
    for (int rp = 0; rp < 4; rp++)
#pragma unroll
        for (int jc = 0; jc < 4; jc++) {
            float v0, v1; unpack2(acc[rp * 4 + jc], v0, v1);
            vals[(2 * rp) * 4 + jc]     = v0 + zT[(c0 + jc) * 132 + r0 + 2 * rp];
            vals[(2 * rp + 1) * 4 + jc] = v1 + zT[(c0 + jc) * 132 + r0 + 2 * rp + 1];
        }
    __syncthreads();
#pragma unroll
    for (int rr = 0; rr < 8; rr++)
#pragma unroll
        for (int jc = 0; jc < 4; jc++)
            s1f[(r0 + rr) * 66 + c0 + jc] = vals[rr * 4 + jc];
    __syncthreads();

    // LN1 (half the threads) runs while the others stage W1 / W2^T
    if (t < 128) {
        float* rowp = s1f + t * 66;
        float s = 0.0f, s2 = 0.0f;
        for (int c = 0; c < 64; c++) { float v = rowp[c]; s += v; s2 += v * v; }
        float m = s * (1.0f / 64.0f);
        float inv = rsqrtf(s2 * (1.0f / 64.0f) - m * m + 1e-5f);
        for (int c = 0; c < 64; c++)
            rowp[c] = (rowp[c] - m) * inv * par[c] + par[64 + c];
    } else {
        const int t2 = t - 128;
        for (int idx = t2; idx < 128 * 64; idx += 128) {
            int f = idx >> 6, c = idx & 63;
            w1s[f * 66 + c] = W1[idx];
        }
        for (int idx = t2; idx < 64 * 128; idx += 128) {
            int c = idx >> 7, f = idx & 127;
            w2t[f * 66 + c] = W2[idx];
        }
    }
    __syncthreads();

    // ---- phase C1: FF1 -> gelu -> h1s ----
    const int r = t >> 1;
    const int p = t & 1;
    {
        u64 s1r[32];
        const u64* srow = (const u64*)(s1f + r * 66);
#pragma unroll
        for (int cc = 0; cc < 32; cc++) s1r[cc] = srow[cc];
        for (int f0 = 0; f0 < 64; f0++) {
            int f = p * 64 + f0;
            u64 a = 0ull;
            const u64* wrow = (const u64*)(w1s + f * 66);
#pragma unroll
            for (int cc = 0; cc < 32; cc++) a = fma2(s1r[cc], wrow[cc], a);
            float v = hadd2(a) + par[256 + f];
            h1s[r * 129 + f] = 0.5f * v * (1.0f + erff(v * 0.70710678118654752f));
        }
    }
    __syncthreads();

    // ---- phase C2: FF2 + residual + LN2 (register LN via shfl partner) ----
    {
        u64 acc3[16];
#pragma unroll
        for (int u = 0; u < 16; u++) {
            int c = p * 32 + 2 * u;
            acc3[u] = pack2(s1f[r * 66 + c] + par[384 + c],
                            s1f[r * 66 + c + 1] + par[384 + c + 1]);
        }
        const float* hrow = h1s + r * 129;
        for (int f = 0; f < 128; f++) {
            u64 a2 = bcast2(hrow[f]);
            const u64* wrow = (const u64*)(w2t + f * 66) + p * 16;
#pragma unroll
            for (int u = 0; u < 16; u++) acc3[u] = fma2(a2, wrow[u], acc3[u]);
        }
        float ov[32];
        float s = 0.0f, s2 = 0.0f;
#pragma unroll
        for (int u = 0; u < 16; u++) {
            float x0, x1; unpack2(acc3[u], x0, x1);
            ov[2 * u] = x0; ov[2 * u + 1] = x1;
            s += x0 + x1; s2 += x0 * x0 + x1 * x1;
        }
        s  += __shfl_xor_sync(0xffffffffu, s, 1);
        s2 += __shfl_xor_sync(0xffffffffu, s2, 1);
        float m = s * (1.0f / 64.0f);
        float inv = rsqrtf(s2 * (1.0f / 64.0f) - m * m + 1e-5f);
#pragma unroll
        for (int u = 0; u < 32; u++)
            ov[u] = (ov[u] - m) * inv * par[128 + p * 32 + u] + par[192 + p * 32 + u];

        const int grow = row0 + r;
        float2* op2 = (float2*)(outp + (size_t)grow * HID + p * 32);
#pragma unroll
        for (int u = 0; u < 16; u++) op2[u] = make_float2(ov[2 * u], ov[2 * u + 1]);

        if (final_layer && (grow % SEQ) == (SEQ - 1)) {
            float* tp = tail + (grow / SEQ) * HID + p * 32;
#pragma unroll
            for (int u = 0; u < 32; u++) tp[u] = ov[u];
        }
    }
}

// ============================================================================
extern "C" void kernel_launch(void* const* d_in, const int* in_sizes, int n_in,
                              void* d_out, int out_size) {
    const float* x     = (const float*)d_in[0];
    const float* Wih0  = (const float*)d_in[1];
    const float* Whh0  = (const float*)d_in[2];
    const float* bih0  = (const float*)d_in[3];
    const float* bhh0  = (const float*)d_in[4];
    const float* Wih1  = (const float*)d_in[5];
    const float* Whh1  = (const float*)d_in[6];
    const float* bih1  = (const float*)d_in[7];
    const float* bhh1  = (const float*)d_in[8];
    const float* coeffs= (const float*)d_in[9];
    const float* ln1_g = (const float*)d_in[10];
    const float* ln1_b = (const float*)d_in[11];
    const float* W1    = (const float*)d_in[12];
    const float* b1    = (const float*)d_in[13];
    const float* W2    = (const float*)d_in[14];
    const float* b2    = (const float*)d_in[15];
    const float* ln2_g = (const float*)d_in[16];
    const float* ln2_b = (const float*)d_in[17];
    float* out = (float*)d_out;

    cudaFuncSetAttribute(k_sindy, cudaFuncAttributeMaxDynamicSharedMemorySize, SINDY_SMEM);

    k_xp0<<<500, 192>>>(x, Wih0, bih0);
    k_gru<<<32, 384>>>(Whh0, Wih1, Whh1, bhh0, bih1, bhh1);

    for (int l = 0; l < 2; l++) {
        k_sindy<<<125, 256, SINDY_SMEM>>>(l, out,
            coeffs + (size_t)l * NLIB * HID,
            ln1_g + l * HID, ln1_b + l * HID,
            W1 + (size_t)l * FFD * HID, b1 + l * FFD,
            W2 + (size_t)l * HID * FFD, b2 + l * HID,
            ln2_g + l * HID, ln2_b + l * HID);
    }
}